// round 4
// baseline (speedup 1.0000x reference)
#include <cuda_runtime.h>
#include <cuda_fp16.h>
#include <cstdint>

#define T_TOK 8192
#define DDIM  1024
#define FDIM  4096
#define NEXP  8
#define LN_EPS 1e-5f

// ---------------- scratch (static device globals; no allocations) ----------
__device__ __half g_Xh[(size_t)T_TOK * DDIM];   // layernormed tokens, fp16
__device__ __half g_Hh[(size_t)T_TOK * FDIM];   // expert hidden, fp16
__device__ __half g_W1h[(size_t)NEXP * DDIM * FDIM]; // W1 fp16 [E][D][F]
__device__ __half g_W2h[(size_t)NEXP * FDIM * DDIM]; // W2 fp16 [E][F][D]
__device__ int    g_perm[NEXP * T_TOK];
__device__ int    g_cnt[NEXP];
__device__ float  g_gate[T_TOK];

// ---------------------------------------------------------------------------
__global__ void zero_cnt_kernel() {
    if (threadIdx.x < NEXP) g_cnt[threadIdx.x] = 0;
}

// fp32 -> fp16 elementwise convert (vectorized)
__global__ void cvt_half_kernel(const float* __restrict__ src,
                                __half* __restrict__ dst, int n4) {
    int i = blockIdx.x * blockDim.x + threadIdx.x;
    if (i < n4) {
        float4 v = reinterpret_cast<const float4*>(src)[i];
        __half2 h0 = __floats2half2_rn(v.x, v.y);
        __half2 h1 = __floats2half2_rn(v.z, v.w);
        reinterpret_cast<__half2*>(dst)[2 * i + 0] = h0;
        reinterpret_cast<__half2*>(dst)[2 * i + 1] = h1;
    }
}

// one block (256 thr) per token: router logits + softmax/argmax + layernorm
__global__ void router_ln_kernel(const float* __restrict__ x,
                                 const float* __restrict__ Wr,
                                 const float* __restrict__ br,
                                 const float* __restrict__ ln_g,
                                 const float* __restrict__ ln_b) {
    const int t   = blockIdx.x;
    const int tid = threadIdx.x;
    const float* xr = x + (size_t)t * DDIM;

    float v[4];
    float sum = 0.f, sumsq = 0.f;
    float lg[8];
#pragma unroll
    for (int e = 0; e < 8; e++) lg[e] = 0.f;

#pragma unroll
    for (int k = 0; k < 4; k++) {
        const int d = tid + 256 * k;
        const float xv = xr[d];
        v[k] = xv;
        sum += xv;
        sumsq += xv * xv;
        const float4* w4 = reinterpret_cast<const float4*>(Wr + (size_t)d * 8);
        const float4 w0 = w4[0];
        const float4 w1 = w4[1];
        lg[0] += xv * w0.x; lg[1] += xv * w0.y; lg[2] += xv * w0.z; lg[3] += xv * w0.w;
        lg[4] += xv * w1.x; lg[5] += xv * w1.y; lg[6] += xv * w1.z; lg[7] += xv * w1.w;
    }

#pragma unroll
    for (int off = 16; off > 0; off >>= 1) {
        sum   += __shfl_xor_sync(0xffffffffu, sum, off);
        sumsq += __shfl_xor_sync(0xffffffffu, sumsq, off);
#pragma unroll
        for (int e = 0; e < 8; e++)
            lg[e] += __shfl_xor_sync(0xffffffffu, lg[e], off);
    }

    __shared__ float red[8][10];
    __shared__ float bc[2];
    const int lane = tid & 31, warp = tid >> 5;
    if (lane == 0) {
        red[warp][0] = sum;
        red[warp][1] = sumsq;
#pragma unroll
        for (int e = 0; e < 8; e++) red[warp][2 + e] = lg[e];
    }
    __syncthreads();

    if (tid == 0) {
        float s = 0.f, ss = 0.f, L[8];
#pragma unroll
        for (int e = 0; e < 8; e++) L[e] = 0.f;
        for (int w = 0; w < 8; w++) {
            s  += red[w][0];
            ss += red[w][1];
#pragma unroll
            for (int e = 0; e < 8; e++) L[e] += red[w][2 + e];
        }
        const float mu  = s * (1.0f / DDIM);
        const float var = ss * (1.0f / DDIM) - mu * mu;
        const float rstd = rsqrtf(var + LN_EPS);

        float lmax = -3.4e38f;
        int idx = 0;
#pragma unroll
        for (int e = 0; e < 8; e++) {
            const float le = L[e] + br[e];
            if (le > lmax) { lmax = le; idx = e; }
        }
        float denom = 0.f;
#pragma unroll
        for (int e = 0; e < 8; e++) denom += expf(L[e] + br[e] - lmax);
        const float gate = 1.0f / denom;

        const int slot = atomicAdd(&g_cnt[idx], 1);
        g_perm[idx * T_TOK + slot] = t;
        g_gate[t] = gate;
        bc[0] = mu;
        bc[1] = rstd;
    }
    __syncthreads();

    const float mu = bc[0], rstd = bc[1];
#pragma unroll
    for (int k = 0; k < 4; k++) {
        const int d = tid + 256 * k;
        g_Xh[(size_t)t * DDIM + d] =
            __float2half_rn((v[k] - mu) * rstd * ln_g[d] + ln_b[d]);
    }
}

// ---------------------------------------------------------------------------
__device__ __forceinline__ void cp_async16(void* dst, const void* src, int srcsz) {
    uint32_t d = (uint32_t)__cvta_generic_to_shared(dst);
    asm volatile("cp.async.cg.shared.global [%0], [%1], 16, %2;\n"
                 :: "r"(d), "l"(src), "r"(srcsz));
}
__device__ __forceinline__ void ldsm_x4(uint32_t& r0, uint32_t& r1,
                                        uint32_t& r2, uint32_t& r3,
                                        const void* p) {
    uint32_t a = (uint32_t)__cvta_generic_to_shared(p);
    asm volatile("ldmatrix.sync.aligned.m8n8.x4.shared.b16 {%0,%1,%2,%3}, [%4];"
                 : "=r"(r0), "=r"(r1), "=r"(r2), "=r"(r3) : "r"(a));
}
__device__ __forceinline__ void ldsm_x2t(uint32_t& r0, uint32_t& r1, const void* p) {
    uint32_t a = (uint32_t)__cvta_generic_to_shared(p);
    asm volatile("ldmatrix.sync.aligned.m8n8.x2.trans.shared.b16 {%0,%1}, [%2];"
                 : "=r"(r0), "=r"(r1) : "r"(a));
}
__device__ __forceinline__ void mma_f16(float c[4], const uint32_t a[4],
                                        const uint32_t b[2]) {
    asm volatile(
        "mma.sync.aligned.m16n8k16.row.col.f32.f16.f16.f32 "
        "{%0,%1,%2,%3}, {%4,%5,%6,%7}, {%8,%9}, {%0,%1,%2,%3};\n"
        : "+f"(c[0]), "+f"(c[1]), "+f"(c[2]), "+f"(c[3])
        : "r"(a[0]), "r"(a[1]), "r"(a[2]), "r"(a[3]), "r"(b[0]), "r"(b[1]));
}

// smem geometry (in halves). K-chunk = 64.
#define KC 64
#define A_STRIDE 72    // 64 k-halves + 8 pad  = 144B rows
#define B_STRIDE 136   // 128 n-halves + 8 pad = 272B rows
#define A_STG (128 * A_STRIDE)   // 9216 halves
#define B_STG (KC * B_STRIDE)    // 8704 halves
#define NSTG 3

// Grouped expert GEMM, fp16 operands, fp32 accum, 128x128 tile, K-chunk 64.
// FIRST=true : A = g_Xh gathered, B = g_W1h[e], epilogue relu(+b1) -> g_Hh (fp16)
// FIRST=false: A = g_Hh gathered, B = g_W2h[e], epilogue (+b2)*gate -> Out (fp32)
template <int KD, int ND, bool FIRST>
__global__ __launch_bounds__(256, 2)
void moe_gemm_kernel(const __half* __restrict__ Bsrc,
                     const float* __restrict__ bias,
                     float* __restrict__ OutParam) {
    const int e   = blockIdx.z;
    const int cnt = g_cnt[e];
    const int m0  = blockIdx.y * 128;
    if (m0 >= cnt) return;
    const int n0  = blockIdx.x * 128;
    const int tid = threadIdx.x;

    const __half* Asrc = FIRST ? g_Xh : g_Hh;

    extern __shared__ __half smem[];
    __half* Asm = smem;                   // [NSTG][128][A_STRIDE]
    __half* Bsm = smem + NSTG * A_STG;    // [NSTG][KC][B_STRIDE]

    // A loads: thread t serves row t>>1, 4 chunks of 16B (64 halves/row)
    const int rA = tid >> 1;
    const int cA0 = (tid & 1) * 4;
    const int gmA = m0 + rA;
    const int tokA = (gmA < cnt) ? g_perm[e * T_TOK + gmA] : -1;
    const __half* a_src = (tokA >= 0) ? Asrc + (size_t)tokA * KD : Asrc;
    const int a_ok = (tokA >= 0) ? 16 : 0;
    // B loads: thread t serves row t>>2 (64 rows), 4 chunks of 16B (128 halves/row)
    const int rB = tid >> 2;
    const int cB0 = (tid & 3) * 4;
    const __half* Bbase = Bsrc + (size_t)e * KD * ND + n0;

    const int warp = tid >> 5, lane = tid & 31;
    const int wm = (warp >> 2) * 64;   // 0 / 64
    const int wn = (warp & 3) * 32;    // 0..96

    float acc[4][4][4];
#pragma unroll
    for (int mi = 0; mi < 4; mi++)
#pragma unroll
        for (int ni = 0; ni < 4; ni++)
#pragma unroll
            for (int r = 0; r < 4; r++) acc[mi][ni][r] = 0.f;

    auto load_stage = [&](int kt, int buf) {
        const int kbase = kt * KC;
        __half* adst = Asm + buf * A_STG + rA * A_STRIDE;
        const __half* as = a_src + kbase;
#pragma unroll
        for (int j = 0; j < 4; j++) {
            const int c = cA0 + j;
            cp_async16(adst + c * 8, as + c * 8, a_ok);
        }
        __half* bdst = Bsm + buf * B_STG + rB * B_STRIDE;
        const __half* bs = Bbase + (size_t)(kbase + rB) * ND;
#pragma unroll
        for (int j = 0; j < 4; j++) {
            const int c = cB0 + j;
            cp_async16(bdst + c * 8, bs + c * 8, 16);
        }
        asm volatile("cp.async.commit_group;\n" ::: "memory");
    };

    constexpr int KT = KD / KC;
#pragma unroll
    for (int s = 0; s < NSTG; s++) load_stage(s, s);

    for (int kt = 0; kt < KT; kt++) {
        const int buf = kt % NSTG;
        asm volatile("cp.async.wait_group 2;\n" ::: "memory");
        __syncthreads();

        const __half* Ab = Asm + buf * A_STG;
        const __half* Bb = Bsm + buf * B_STG;

#pragma unroll
        for (int ks = 0; ks < 4; ks++) {
            const int kk = ks * 16;
            uint32_t afr[4][4];
#pragma unroll
            for (int mi = 0; mi < 4; mi++) {
                const int row = wm + mi * 16 + (lane & 15);
                const int col = kk + (lane >> 4) * 8;
                ldsm_x4(afr[mi][0], afr[mi][1], afr[mi][2], afr[mi][3],
                        Ab + row * A_STRIDE + col);
            }
            uint32_t bfr[4][2];
#pragma unroll
            for (int ni = 0; ni < 4; ni++) {
                const int row = kk + (lane & 15);
                const int col = wn + ni * 8;
                ldsm_x2t(bfr[ni][0], bfr[ni][1], Bb + row * B_STRIDE + col);
            }
#pragma unroll
            for (int mi = 0; mi < 4; mi++)
#pragma unroll
                for (int ni = 0; ni < 4; ni++)
                    mma_f16(acc[mi][ni], afr[mi], bfr[ni]);
        }
        __syncthreads();
        if (kt + NSTG < KT) load_stage(kt + NSTG, buf);
    }

    // epilogue
    const float* bvec = bias + (size_t)e * ND + n0;
#pragma unroll
    for (int mi = 0; mi < 4; mi++) {
#pragma unroll
        for (int r = 0; r < 2; r++) {
            const int row = wm + mi * 16 + (lane >> 2) + r * 8;
            const int gm = m0 + row;
            if (gm >= cnt) continue;
            const int tok = g_perm[e * T_TOK + gm];
            if (FIRST) {
                __half* orow = g_Hh + (size_t)tok * ND + n0;
#pragma unroll
                for (int ni = 0; ni < 4; ni++) {
                    const int ccol = wn + ni * 8 + (lane & 3) * 2;
                    float v0 = fmaxf(acc[mi][ni][r * 2 + 0] + bvec[ccol], 0.f);
                    float v1 = fmaxf(acc[mi][ni][r * 2 + 1] + bvec[ccol + 1], 0.f);
                    *reinterpret_cast<__half2*>(&orow[ccol]) =
                        __floats2half2_rn(v0, v1);
                }
            } else {
                const float gscale = g_gate[tok];
                float* orow = OutParam + (size_t)tok * ND + n0;
#pragma unroll
                for (int ni = 0; ni < 4; ni++) {
                    const int ccol = wn + ni * 8 + (lane & 3) * 2;
                    float v0 = (acc[mi][ni][r * 2 + 0] + bvec[ccol]) * gscale;
                    float v1 = (acc[mi][ni][r * 2 + 1] + bvec[ccol + 1]) * gscale;
                    *reinterpret_cast<float2*>(&orow[ccol]) = make_float2(v0, v1);
                }
            }
        }
    }
}

// ---------------------------------------------------------------------------
extern "C" void kernel_launch(void* const* d_in, const int* in_sizes, int n_in,
                              void* d_out, int out_size) {
    const float* x    = (const float*)d_in[0];
    const float* Wr   = (const float*)d_in[1];
    const float* br   = (const float*)d_in[2];
    const float* ln_g = (const float*)d_in[3];
    const float* ln_b = (const float*)d_in[4];
    const float* W1   = (const float*)d_in[5];
    const float* b1   = (const float*)d_in[6];
    const float* W2   = (const float*)d_in[7];
    const float* b2   = (const float*)d_in[8];
    float* out = (float*)d_out;

    const size_t smem = (size_t)NSTG * (A_STG + B_STG) * sizeof(__half); // 107520 B
    cudaFuncSetAttribute(moe_gemm_kernel<DDIM, FDIM, true>,
                         cudaFuncAttributeMaxDynamicSharedMemorySize, (int)smem);
    cudaFuncSetAttribute(moe_gemm_kernel<FDIM, DDIM, false>,
                         cudaFuncAttributeMaxDynamicSharedMemorySize, (int)smem);

    zero_cnt_kernel<<<1, 32>>>();

    __half* w1h;  cudaGetSymbolAddress((void**)&w1h, g_W1h);
    __half* w2h;  cudaGetSymbolAddress((void**)&w2h, g_W2h);
    const int n4 = NEXP * DDIM * FDIM / 4;   // 8388608
    cvt_half_kernel<<<(n4 + 255) / 256, 256>>>(W1, w1h, n4);
    cvt_half_kernel<<<(n4 + 255) / 256, 256>>>(W2, w2h, n4);

    router_ln_kernel<<<T_TOK, 256>>>(x, Wr, br, ln_g, ln_b);

    dim3 g1(FDIM / 128, T_TOK / 128, NEXP);
    moe_gemm_kernel<DDIM, FDIM, true><<<g1, 256, smem>>>(w1h, b1, nullptr);

    dim3 g2(DDIM / 128, T_TOK / 128, NEXP);
    moe_gemm_kernel<FDIM, DDIM, false><<<g2, 256, smem>>>(w2h, b2, out);
}

// round 5
// speedup vs baseline: 1.2001x; 1.2001x over previous
#include <cuda_runtime.h>
#include <cuda_fp16.h>
#include <cstdint>

#define T_TOK 8192
#define DDIM  1024
#define FDIM  4096
#define NEXP  8
#define LN_EPS 1e-5f

// ---------------- scratch (static device globals; no allocations) ----------
__device__ __half g_Xh[(size_t)T_TOK * DDIM];   // layernormed tokens, fp16
__device__ __half g_Hh[(size_t)T_TOK * FDIM];   // expert hidden, fp16
__device__ __half g_W1h[(size_t)NEXP * DDIM * FDIM]; // W1 fp16 [E][D][F]
__device__ __half g_W2h[(size_t)NEXP * FDIM * DDIM]; // W2 fp16 [E][F][D]
__device__ int    g_perm[NEXP * T_TOK];
__device__ int    g_cnt[NEXP];
__device__ float  g_gate[T_TOK];

// ---------------------------------------------------------------------------
__global__ void zero_cnt_kernel() {
    if (threadIdx.x < NEXP) g_cnt[threadIdx.x] = 0;
}

// fp32 -> fp16 elementwise convert (vectorized)
__global__ void cvt_half_kernel(const float* __restrict__ src,
                                __half* __restrict__ dst, int n4) {
    int i = blockIdx.x * blockDim.x + threadIdx.x;
    if (i < n4) {
        float4 v = reinterpret_cast<const float4*>(src)[i];
        __half2 h0 = __floats2half2_rn(v.x, v.y);
        __half2 h1 = __floats2half2_rn(v.z, v.w);
        reinterpret_cast<__half2*>(dst)[2 * i + 0] = h0;
        reinterpret_cast<__half2*>(dst)[2 * i + 1] = h1;
    }
}

// one block (256 thr) per token: router logits + softmax/argmax + layernorm
__global__ void router_ln_kernel(const float* __restrict__ x,
                                 const float* __restrict__ Wr,
                                 const float* __restrict__ br,
                                 const float* __restrict__ ln_g,
                                 const float* __restrict__ ln_b) {
    const int t   = blockIdx.x;
    const int tid = threadIdx.x;
    const float* xr = x + (size_t)t * DDIM;

    float v[4];
    float sum = 0.f, sumsq = 0.f;
    float lg[8];
#pragma unroll
    for (int e = 0; e < 8; e++) lg[e] = 0.f;

#pragma unroll
    for (int k = 0; k < 4; k++) {
        const int d = tid + 256 * k;
        const float xv = xr[d];
        v[k] = xv;
        sum += xv;
        sumsq += xv * xv;
        const float4* w4 = reinterpret_cast<const float4*>(Wr + (size_t)d * 8);
        const float4 w0 = w4[0];
        const float4 w1 = w4[1];
        lg[0] += xv * w0.x; lg[1] += xv * w0.y; lg[2] += xv * w0.z; lg[3] += xv * w0.w;
        lg[4] += xv * w1.x; lg[5] += xv * w1.y; lg[6] += xv * w1.z; lg[7] += xv * w1.w;
    }

#pragma unroll
    for (int off = 16; off > 0; off >>= 1) {
        sum   += __shfl_xor_sync(0xffffffffu, sum, off);
        sumsq += __shfl_xor_sync(0xffffffffu, sumsq, off);
#pragma unroll
        for (int e = 0; e < 8; e++)
            lg[e] += __shfl_xor_sync(0xffffffffu, lg[e], off);
    }

    __shared__ float red[8][10];
    __shared__ float bc[2];
    const int lane = tid & 31, warp = tid >> 5;
    if (lane == 0) {
        red[warp][0] = sum;
        red[warp][1] = sumsq;
#pragma unroll
        for (int e = 0; e < 8; e++) red[warp][2 + e] = lg[e];
    }
    __syncthreads();

    if (tid == 0) {
        float s = 0.f, ss = 0.f, L[8];
#pragma unroll
        for (int e = 0; e < 8; e++) L[e] = 0.f;
        for (int w = 0; w < 8; w++) {
            s  += red[w][0];
            ss += red[w][1];
#pragma unroll
            for (int e = 0; e < 8; e++) L[e] += red[w][2 + e];
        }
        const float mu  = s * (1.0f / DDIM);
        const float var = ss * (1.0f / DDIM) - mu * mu;
        const float rstd = rsqrtf(var + LN_EPS);

        float lmax = -3.4e38f;
        int idx = 0;
#pragma unroll
        for (int e = 0; e < 8; e++) {
            const float le = L[e] + br[e];
            if (le > lmax) { lmax = le; idx = e; }
        }
        float denom = 0.f;
#pragma unroll
        for (int e = 0; e < 8; e++) denom += expf(L[e] + br[e] - lmax);
        const float gate = 1.0f / denom;

        const int slot = atomicAdd(&g_cnt[idx], 1);
        g_perm[idx * T_TOK + slot] = t;
        g_gate[t] = gate;
        bc[0] = mu;
        bc[1] = rstd;
    }
    __syncthreads();

    const float mu = bc[0], rstd = bc[1];
#pragma unroll
    for (int k = 0; k < 4; k++) {
        const int d = tid + 256 * k;
        g_Xh[(size_t)t * DDIM + d] =
            __float2half_rn((v[k] - mu) * rstd * ln_g[d] + ln_b[d]);
    }
}

// ---------------------------------------------------------------------------
__device__ __forceinline__ void cp_async16(void* dst, const void* src, int srcsz) {
    uint32_t d = (uint32_t)__cvta_generic_to_shared(dst);
    asm volatile("cp.async.cg.shared.global [%0], [%1], 16, %2;\n"
                 :: "r"(d), "l"(src), "r"(srcsz));
}
__device__ __forceinline__ void ldsm_x4(uint32_t& r0, uint32_t& r1,
                                        uint32_t& r2, uint32_t& r3,
                                        const void* p) {
    uint32_t a = (uint32_t)__cvta_generic_to_shared(p);
    asm volatile("ldmatrix.sync.aligned.m8n8.x4.shared.b16 {%0,%1,%2,%3}, [%4];"
                 : "=r"(r0), "=r"(r1), "=r"(r2), "=r"(r3) : "r"(a));
}
__device__ __forceinline__ void ldsm_x4t(uint32_t& r0, uint32_t& r1,
                                         uint32_t& r2, uint32_t& r3,
                                         const void* p) {
    uint32_t a = (uint32_t)__cvta_generic_to_shared(p);
    asm volatile("ldmatrix.sync.aligned.m8n8.x4.trans.shared.b16 {%0,%1,%2,%3}, [%4];"
                 : "=r"(r0), "=r"(r1), "=r"(r2), "=r"(r3) : "r"(a));
}
__device__ __forceinline__ void mma_f16(float c[4], const uint32_t a[4],
                                        const uint32_t b[2]) {
    asm volatile(
        "mma.sync.aligned.m16n8k16.row.col.f32.f16.f16.f32 "
        "{%0,%1,%2,%3}, {%4,%5,%6,%7}, {%8,%9}, {%0,%1,%2,%3};\n"
        : "+f"(c[0]), "+f"(c[1]), "+f"(c[2]), "+f"(c[3])
        : "r"(a[0]), "r"(a[1]), "r"(a[2]), "r"(a[3]), "r"(b[0]), "r"(b[1]));
}

// smem strides (in halves), padded for conflict-free ldmatrix  (R2-proven geometry)
#define A_STRIDE 40   // 32 k-halves + 8 pad = 80B rows
#define B_STRIDE 136  // 128 n-halves + 8 pad = 272B rows
#define A_STG (128 * A_STRIDE)  // 5120 halves
#define B_STG (32 * B_STRIDE)   // 4352 halves
#define NSTAGE 4

// Grouped expert GEMM, fp16 operands, fp32 accum.
// FIRST=true : A = g_Xh gathered, B = g_W1h[e], epilogue relu(+b1) -> g_Hh (fp16)
// FIRST=false: A = g_Hh gathered, B = g_W2h[e], epilogue (+b2)*gate -> Out (fp32)
template <int KD, int ND, bool FIRST>
__global__ __launch_bounds__(256, 2)
void moe_gemm_kernel(const __half* __restrict__ Bsrc,
                     const float* __restrict__ bias,
                     float* __restrict__ OutParam) {
    const int e   = blockIdx.z;
    const int cnt = g_cnt[e];
    const int m0  = blockIdx.y * 128;
    if (m0 >= cnt) return;
    const int n0  = blockIdx.x * 128;
    const int tid = threadIdx.x;

    const __half* Asrc = FIRST ? g_Xh : g_Hh;

    extern __shared__ __half smem[];
    __half* Asm = smem;                   // [NSTAGE][128][A_STRIDE]
    __half* Bsm = smem + NSTAGE * A_STG;  // [NSTAGE][32][B_STRIDE]

    // A loads: thread t serves row t>>1, 2 chunks of 16B
    const int rA = tid >> 1;
    const int cA = (tid & 1) * 2;
    const int gmA = m0 + rA;
    const int tokA = (gmA < cnt) ? g_perm[e * T_TOK + gmA] : -1;
    // B loads: thread t serves row t>>3, 2 chunks of 16B
    const int rB = tid >> 3;
    const int cB = (tid & 7) * 2;
    const __half* Bbase = Bsrc + (size_t)e * KD * ND + n0;

    const int warp = tid >> 5, lane = tid & 31;
    const int wm = (warp >> 2) * 64;   // 0 / 64
    const int wn = (warp & 3) * 32;    // 0..96

    float acc[4][4][4];
#pragma unroll
    for (int mi = 0; mi < 4; mi++)
#pragma unroll
        for (int ni = 0; ni < 4; ni++)
#pragma unroll
            for (int r = 0; r < 4; r++) acc[mi][ni][r] = 0.f;

    auto load_stage = [&](int kt, int buf) {
        const int kbase = kt * 32;
        __half* adst = Asm + buf * A_STG + rA * A_STRIDE + cA * 8;
        const __half* asrc = (tokA >= 0)
            ? (Asrc + (size_t)tokA * KD + kbase + cA * 8) : Asrc;
        cp_async16(adst,      asrc,     (tokA >= 0) ? 16 : 0);
        cp_async16(adst + 8,  asrc + 8, (tokA >= 0) ? 16 : 0);
        __half* bdst = Bsm + buf * B_STG + rB * B_STRIDE + cB * 8;
        const __half* bsrc = Bbase + (size_t)(kbase + rB) * ND + cB * 8;
        cp_async16(bdst,     bsrc,     16);
        cp_async16(bdst + 8, bsrc + 8, 16);
        asm volatile("cp.async.commit_group;\n" ::: "memory");
    };

    constexpr int KT = KD / 32;
#pragma unroll
    for (int s = 0; s < NSTAGE - 1; s++) load_stage(s, s);

    for (int kt = 0; kt < KT; kt++) {
        const int buf = kt & (NSTAGE - 1);
        const int rem = KT - 1 - kt;
        if (rem >= 2)      asm volatile("cp.async.wait_group 2;\n" ::: "memory");
        else if (rem == 1) asm volatile("cp.async.wait_group 1;\n" ::: "memory");
        else               asm volatile("cp.async.wait_group 0;\n" ::: "memory");
        __syncthreads();   // single barrier per iteration: also guards WAR for the
                           // load below (buffer (kt+3)%4 was read at iter kt-1,
                           // which every thread finished before this sync)
        if (kt + NSTAGE - 1 < KT)
            load_stage(kt + NSTAGE - 1, (kt + NSTAGE - 1) & (NSTAGE - 1));

        const __half* Ab = Asm + buf * A_STG;
        const __half* Bb = Bsm + buf * B_STG;

#pragma unroll
        for (int ks = 0; ks < 2; ks++) {
            const int kk = ks * 16;
            uint32_t afr[4][4];
#pragma unroll
            for (int mi = 0; mi < 4; mi++) {
                const int row = wm + mi * 16 + (lane & 15);
                const int col = kk + (lane >> 4) * 8;
                ldsm_x4(afr[mi][0], afr[mi][1], afr[mi][2], afr[mi][3],
                        Ab + row * A_STRIDE + col);
            }
            uint32_t bfr[4][2];
#pragma unroll
            for (int pr = 0; pr < 2; pr++) {
                const int row = kk + (lane & 15);
                const int col = wn + pr * 16 + (lane >> 4) * 8;
                ldsm_x4t(bfr[2 * pr][0], bfr[2 * pr][1],
                         bfr[2 * pr + 1][0], bfr[2 * pr + 1][1],
                         Bb + row * B_STRIDE + col);
            }
#pragma unroll
            for (int mi = 0; mi < 4; mi++)
#pragma unroll
                for (int ni = 0; ni < 4; ni++)
                    mma_f16(acc[mi][ni], afr[mi], bfr[ni]);
        }
    }

    // epilogue
    const float* bvec = bias + (size_t)e * ND + n0;
#pragma unroll
    for (int mi = 0; mi < 4; mi++) {
#pragma unroll
        for (int r = 0; r < 2; r++) {
            const int row = wm + mi * 16 + (lane >> 2) + r * 8;
            const int gm = m0 + row;
            if (gm >= cnt) continue;
            const int tok = g_perm[e * T_TOK + gm];
            if (FIRST) {
                __half* orow = g_Hh + (size_t)tok * ND + n0;
#pragma unroll
                for (int ni = 0; ni < 4; ni++) {
                    const int ccol = wn + ni * 8 + (lane & 3) * 2;
                    float v0 = fmaxf(acc[mi][ni][r * 2 + 0] + bvec[ccol], 0.f);
                    float v1 = fmaxf(acc[mi][ni][r * 2 + 1] + bvec[ccol + 1], 0.f);
                    *reinterpret_cast<__half2*>(&orow[ccol]) =
                        __floats2half2_rn(v0, v1);
                }
            } else {
                const float gscale = g_gate[tok];
                float* orow = OutParam + (size_t)tok * ND + n0;
#pragma unroll
                for (int ni = 0; ni < 4; ni++) {
                    const int ccol = wn + ni * 8 + (lane & 3) * 2;
                    float v0 = (acc[mi][ni][r * 2 + 0] + bvec[ccol]) * gscale;
                    float v1 = (acc[mi][ni][r * 2 + 1] + bvec[ccol + 1]) * gscale;
                    *reinterpret_cast<float2*>(&orow[ccol]) = make_float2(v0, v1);
                }
            }
        }
    }
}

// ---------------------------------------------------------------------------
extern "C" void kernel_launch(void* const* d_in, const int* in_sizes, int n_in,
                              void* d_out, int out_size) {
    const float* x    = (const float*)d_in[0];
    const float* Wr   = (const float*)d_in[1];
    const float* br   = (const float*)d_in[2];
    const float* ln_g = (const float*)d_in[3];
    const float* ln_b = (const float*)d_in[4];
    const float* W1   = (const float*)d_in[5];
    const float* b1   = (const float*)d_in[6];
    const float* W2   = (const float*)d_in[7];
    const float* b2   = (const float*)d_in[8];
    float* out = (float*)d_out;

    const size_t smem = (size_t)NSTAGE * (A_STG + B_STG) * sizeof(__half); // 75776 B
    cudaFuncSetAttribute(moe_gemm_kernel<DDIM, FDIM, true>,
                         cudaFuncAttributeMaxDynamicSharedMemorySize, (int)smem);
    cudaFuncSetAttribute(moe_gemm_kernel<FDIM, DDIM, false>,
                         cudaFuncAttributeMaxDynamicSharedMemorySize, (int)smem);

    zero_cnt_kernel<<<1, 32>>>();

    __half* w1h;  cudaGetSymbolAddress((void**)&w1h, g_W1h);
    __half* w2h;  cudaGetSymbolAddress((void**)&w2h, g_W2h);
    const int n4 = NEXP * DDIM * FDIM / 4;   // 8388608
    cvt_half_kernel<<<(n4 + 255) / 256, 256>>>(W1, w1h, n4);
    cvt_half_kernel<<<(n4 + 255) / 256, 256>>>(W2, w2h, n4);

    router_ln_kernel<<<T_TOK, 256>>>(x, Wr, br, ln_g, ln_b);

    dim3 g1(FDIM / 128, T_TOK / 128, NEXP);
    moe_gemm_kernel<DDIM, FDIM, true><<<g1, 256, smem>>>(w1h, b1, nullptr);

    dim3 g2(DDIM / 128, T_TOK / 128, NEXP);
    moe_gemm_kernel<FDIM, DDIM, false><<<g2, 256, smem>>>(w2h, b2, out);
}